// round 2
// baseline (speedup 1.0000x reference)
#include <cuda_runtime.h>
#include <cuda_fp16.h>
#include <cstdint>

#define B_  16
#define Q_  256
#define K_  256
#define H_  256
#define DV_ 256

__device__ float g_qp[B_ * Q_ * H_];
__device__ float g_kp[B_ * K_ * H_];
__device__ float g_scores[B_ * Q_ * K_];

// ---------------- packed helpers ----------------
__device__ __forceinline__ unsigned long long pack2(float lo, float hi) {
    unsigned long long r;
    asm("mov.b64 %0, {%1, %2};" : "=l"(r) : "f"(lo), "f"(hi));
    return r;
}
__device__ __forceinline__ float2 unpack2(unsigned long long v) {
    float2 f;
    asm("mov.b64 {%0, %1}, %2;" : "=f"(f.x), "=f"(f.y) : "l"(v));
    return f;
}
__device__ __forceinline__ void ffma2(unsigned long long& acc,
                                      unsigned long long a, unsigned long long b) {
    asm("fma.rn.f32x2 %0, %1, %2, %0;" : "+l"(acc) : "l"(a), "l"(b));
}
// add two packed f32 (q2+k2), convert to f16x2, tanh.  Result = f16x2 bits.
__device__ __forceinline__ unsigned tanh2_sum(unsigned long long q2, unsigned long long k2) {
    unsigned r;
    asm("{\n\t"
        ".reg .b64 s;\n\t"
        ".reg .b32 lo, hi, h2;\n\t"
        "add.rn.f32x2 s, %1, %2;\n\t"
        "mov.b64 {lo, hi}, s;\n\t"
        "cvt.rn.f16x2.f32 h2, hi, lo;\n\t"
        "tanh.approx.f16x2 %0, h2;\n\t"
        "}"
        : "=r"(r) : "l"(q2), "l"(k2));
    return r;
}
__device__ __forceinline__ __half2 as_h2(unsigned u) {
    __half2 h;
    *reinterpret_cast<unsigned*>(&h) = u;
    return h;
}

__device__ __forceinline__ void cp16(uint32_t dst, const void* src) {
    asm volatile("cp.async.cg.shared.global [%0], [%1], 16;" :: "r"(dst), "l"(src));
}

// ---------------------------------------------------------------------------
// Kernel 1: projection GEMM  C[M,256] = A[M,256] * W[256,256]^T   (f32x2 FFMA)
// blockIdx.z: 0 -> queries/W_q -> g_qp ; 1 -> keys/W_k -> g_kp
// ---------------------------------------------------------------------------
__global__ __launch_bounds__(256) void proj_gemm(const float* __restrict__ Aq,
                                                 const float* __restrict__ Wq,
                                                 const float* __restrict__ Ak,
                                                 const float* __restrict__ Wk) {
    constexpr int BM = 64, BN = 64, BK = 32;
    __shared__ __align__(16) float As[BK][BM + 4];  // stride 68 floats (272B)
    __shared__ __align__(16) float Bs[BK][BN + 4];

    const float* A;
    const float* W;
    float* C;
    if (blockIdx.z == 0) { A = Aq; W = Wq; C = g_qp; }
    else                 { A = Ak; W = Wk; C = g_kp; }

    const int tid = threadIdx.x;
    const int m0 = blockIdx.y * BM;
    const int n0 = blockIdx.x * BN;
    const int ty = tid >> 4;       // 0..15
    const int tx = tid & 15;       // 0..15

    // acc2[ip][j]: halves = rows (ty*4+2ip, ty*4+2ip+1), column tx*4+j
    unsigned long long acc2[2][4];
#pragma unroll
    for (int i = 0; i < 2; i++)
#pragma unroll
        for (int j = 0; j < 4; j++) acc2[i][j] = pack2(0.f, 0.f);

    const int lr = tid >> 3;        // 0..31
    const int lc = (tid & 7) * 4;   // 0,4,...,28

    for (int kt = 0; kt < H_; kt += BK) {
        float4 a0 = *(const float4*)&A[(m0 + lr) * H_ + kt + lc];
        float4 a1 = *(const float4*)&A[(m0 + lr + 32) * H_ + kt + lc];
        float4 b0 = *(const float4*)&W[(n0 + lr) * H_ + kt + lc];
        float4 b1 = *(const float4*)&W[(n0 + lr + 32) * H_ + kt + lc];

        As[lc + 0][lr] = a0.x; As[lc + 1][lr] = a0.y;
        As[lc + 2][lr] = a0.z; As[lc + 3][lr] = a0.w;
        As[lc + 0][lr + 32] = a1.x; As[lc + 1][lr + 32] = a1.y;
        As[lc + 2][lr + 32] = a1.z; As[lc + 3][lr + 32] = a1.w;
        Bs[lc + 0][lr] = b0.x; Bs[lc + 1][lr] = b0.y;
        Bs[lc + 2][lr] = b0.z; Bs[lc + 3][lr] = b0.w;
        Bs[lc + 0][lr + 32] = b1.x; Bs[lc + 1][lr + 32] = b1.y;
        Bs[lc + 2][lr + 32] = b1.z; Bs[lc + 3][lr + 32] = b1.w;

        __syncthreads();

#pragma unroll
        for (int kk = 0; kk < BK; kk++) {
            unsigned long long a20 = *(const unsigned long long*)&As[kk][ty * 4];
            unsigned long long a21 = *(const unsigned long long*)&As[kk][ty * 4 + 2];
#pragma unroll
            for (int j = 0; j < 4; j++) {
                float bj = Bs[kk][tx * 4 + j];
                unsigned long long bd = pack2(bj, bj);
                ffma2(acc2[0][j], a20, bd);
                ffma2(acc2[1][j], a21, bd);
            }
        }
        __syncthreads();
    }

    float2 u0[4], u1[4];
#pragma unroll
    for (int j = 0; j < 4; j++) { u0[j] = unpack2(acc2[0][j]); u1[j] = unpack2(acc2[1][j]); }

    float* crow = &C[(m0 + ty * 4) * H_ + n0 + tx * 4];
    *(float4*)&crow[0 * H_] = make_float4(u0[0].x, u0[1].x, u0[2].x, u0[3].x);
    *(float4*)&crow[1 * H_] = make_float4(u0[0].y, u0[1].y, u0[2].y, u0[3].y);
    *(float4*)&crow[2 * H_] = make_float4(u1[0].x, u1[1].x, u1[2].x, u1[3].x);
    *(float4*)&crow[3 * H_] = make_float4(u1[0].y, u1[1].y, u1[2].y, u1[3].y);
}

// ---------------------------------------------------------------------------
// Kernel 2: scores[b,q,k] = sum_h w_v[h] * tanh(qp[b,q,h]+kp[b,k,h])
// f16x2 MUFU tanh, 2 per instruction. 64x64 tile per block, 4x4 per thread.
// ---------------------------------------------------------------------------
__global__ __launch_bounds__(256) void scores_f16(const float* __restrict__ wv) {
    const int b = blockIdx.z;
    const int q0 = blockIdx.y * 64;
    const int k0 = blockIdx.x * 64;

    __shared__ __align__(16) float qs[64][34];   // stride 136B (8B aligned)
    __shared__ __align__(16) float ks[64][34];
    __shared__ __half2 sw2[128];

    const int tid = threadIdx.x;
    if (tid < 128) sw2[tid] = __floats2half2_rn(wv[2 * tid], wv[2 * tid + 1]);

    const int ty = tid >> 4;       // 0..15 -> q rows ty*4..+3
    const int tx = tid & 15;       // 0..15 -> k rows tx*4..+3
    const int lr = tid >> 3;       // 0..31
    const int lc = (tid & 7) * 4;  // 0..28

    const float* qb = g_qp + (b * Q_ + q0) * H_;
    const float* kb = g_kp + (b * K_ + k0) * H_;

    float facc[4][4];
#pragma unroll
    for (int i = 0; i < 4; i++)
#pragma unroll
        for (int j = 0; j < 4; j++) facc[i][j] = 0.f;

    for (int hc = 0; hc < H_; hc += 32) {
        __syncthreads();
        {
            float4 a0 = *(const float4*)&qb[lr * H_ + hc + lc];
            float4 a1 = *(const float4*)&qb[(lr + 32) * H_ + hc + lc];
            float4 c0 = *(const float4*)&kb[lr * H_ + hc + lc];
            float4 c1 = *(const float4*)&kb[(lr + 32) * H_ + hc + lc];
            *(float2*)&qs[lr][lc]          = make_float2(a0.x, a0.y);
            *(float2*)&qs[lr][lc + 2]      = make_float2(a0.z, a0.w);
            *(float2*)&qs[lr + 32][lc]     = make_float2(a1.x, a1.y);
            *(float2*)&qs[lr + 32][lc + 2] = make_float2(a1.z, a1.w);
            *(float2*)&ks[lr][lc]          = make_float2(c0.x, c0.y);
            *(float2*)&ks[lr][lc + 2]      = make_float2(c0.z, c0.w);
            *(float2*)&ks[lr + 32][lc]     = make_float2(c1.x, c1.y);
            *(float2*)&ks[lr + 32][lc + 2] = make_float2(c1.z, c1.w);
        }
        __syncthreads();

#pragma unroll
        for (int g = 0; g < 4; g++) {
            __half2 cacc[4][4];
            const __half2 z2 = __float2half2_rn(0.f);
#pragma unroll
            for (int i = 0; i < 4; i++)
#pragma unroll
                for (int j = 0; j < 4; j++) cacc[i][j] = z2;

#pragma unroll
            for (int s = 0; s < 4; s++) {
                const int h2 = g * 4 + s;
                unsigned long long q2[4], k2[4];
#pragma unroll
                for (int i = 0; i < 4; i++)
                    q2[i] = *(const unsigned long long*)&qs[ty * 4 + i][2 * h2];
#pragma unroll
                for (int j = 0; j < 4; j++)
                    k2[j] = *(const unsigned long long*)&ks[tx * 4 + j][2 * h2];
                __half2 w2 = sw2[(hc >> 1) + h2];
#pragma unroll
                for (int i = 0; i < 4; i++)
#pragma unroll
                    for (int j = 0; j < 4; j++) {
                        unsigned t = tanh2_sum(q2[i], k2[j]);
                        cacc[i][j] = __hfma2(as_h2(t), w2, cacc[i][j]);
                    }
            }
#pragma unroll
            for (int i = 0; i < 4; i++)
#pragma unroll
                for (int j = 0; j < 4; j++) {
                    float2 f = __half22float2(cacc[i][j]);
                    facc[i][j] += f.x + f.y;
                }
        }
    }

    float* sbase = g_scores + (b * Q_ + q0 + ty * 4) * K_ + k0 + tx * 4;
#pragma unroll
    for (int i = 0; i < 4; i++)
        *(float4*)&sbase[i * K_] = make_float4(facc[i][0], facc[i][1], facc[i][2], facc[i][3]);
}

// ---------------------------------------------------------------------------
// Kernel 3: fused row-softmax + out = attn @ V
// Block: 32 q-rows x 128 v-cols. 8 warps; warp = 4 rows; lane = 4 cols.
// V staged via cp.async double buffer; f32x2 FFMA (column-paired).
// ---------------------------------------------------------------------------
__global__ __launch_bounds__(256) void softmax_av(const float* __restrict__ V,
                                                  float* __restrict__ out) {
    const int b = blockIdx.y;
    const int q0 = (blockIdx.x >> 1) * 32;
    const int c0 = (blockIdx.x & 1) * 128;

    __shared__ __align__(16) float sattn[32][256];      // 32 KB
    __shared__ __align__(16) float vs[2][32][132];      // 2 x ~16.5 KB

    const int tid = threadIdx.x;
    const int w = tid >> 5;
    const int lane = tid & 31;

    // ---- softmax: warp w handles rows w, w+8, w+16, w+24 ----
#pragma unroll
    for (int i = 0; i < 4; i++) {
        const int r = w + 8 * i;
        const float* srow = g_scores + (b * Q_ + q0 + r) * K_;
        float v[8];
        float mx = -1e30f;
#pragma unroll
        for (int j = 0; j < 8; j++) {
            v[j] = srow[lane + 32 * j];
            mx = fmaxf(mx, v[j]);
        }
#pragma unroll
        for (int off = 16; off; off >>= 1)
            mx = fmaxf(mx, __shfl_xor_sync(0xffffffffu, mx, off));
        float s = 0.f;
#pragma unroll
        for (int j = 0; j < 8; j++) {
            v[j] = __expf(v[j] - mx);
            s += v[j];
        }
#pragma unroll
        for (int off = 16; off; off >>= 1)
            s += __shfl_xor_sync(0xffffffffu, s, off);
        const float inv = 1.0f / s;
#pragma unroll
        for (int j = 0; j < 8; j++) sattn[r][lane + 32 * j] = v[j] * inv;
    }

    // ---- AV ----
    const int r0 = 4 * w;
    unsigned long long acc2[4][2];
#pragma unroll
    for (int r = 0; r < 4; r++) { acc2[r][0] = pack2(0.f, 0.f); acc2[r][1] = pack2(0.f, 0.f); }

    const int vr = tid >> 3;          // 0..31 (V row within chunk)
    const int vc = (tid & 7) * 16;    // 0..112 (col within 128)

    // stage chunk kc into buffer buf
    auto stage = [&](int kc, int buf) {
        const float* src = V + (size_t)(b * K_ + kc * 32 + vr) * DV_ + c0 + vc;
        uint32_t dst = (uint32_t)__cvta_generic_to_shared(&vs[buf][vr][vc]);
#pragma unroll
        for (int j = 0; j < 4; j++) cp16(dst + j * 16, src + j * 4);
        asm volatile("cp.async.commit_group;");
    };

    stage(0, 0);

    for (int kc = 0; kc < 8; kc++) {
        if (kc < 7) {
            stage(kc + 1, (kc + 1) & 1);
            asm volatile("cp.async.wait_group 1;");
        } else {
            asm volatile("cp.async.wait_group 0;");
        }
        __syncthreads();

        const int buf = kc & 1;
#pragma unroll
        for (int k4 = 0; k4 < 8; k4++) {
            float4 a4[4];
#pragma unroll
            for (int r = 0; r < 4; r++)
                a4[r] = *(const float4*)&sattn[r0 + r][kc * 32 + k4 * 4];
#pragma unroll
            for (int kk = 0; kk < 4; kk++) {
                float4 v = *(const float4*)&vs[buf][k4 * 4 + kk][lane * 4];
                unsigned long long v01 = pack2(v.x, v.y);
                unsigned long long v23 = pack2(v.z, v.w);
#pragma unroll
                for (int r = 0; r < 4; r++) {
                    float av = ((const float*)&a4[r])[kk];
                    unsigned long long ad = pack2(av, av);
                    ffma2(acc2[r][0], ad, v01);
                    ffma2(acc2[r][1], ad, v23);
                }
            }
        }
        __syncthreads();
    }

#pragma unroll
    for (int r = 0; r < 4; r++) {
        float2 p0 = unpack2(acc2[r][0]);
        float2 p1 = unpack2(acc2[r][1]);
        *(float4*)&out[(size_t)(b * Q_ + q0 + r0 + r) * DV_ + c0 + lane * 4] =
            make_float4(p0.x, p0.y, p1.x, p1.y);
    }
}

// ---------------------------------------------------------------------------
extern "C" void kernel_launch(void* const* d_in, const int* in_sizes, int n_in,
                              void* d_out, int out_size) {
    const float* queries = (const float*)d_in[0];
    const float* keys    = (const float*)d_in[1];
    const float* values  = (const float*)d_in[2];
    const float* W_q     = (const float*)d_in[3];
    const float* W_k     = (const float*)d_in[4];
    const float* w_v     = (const float*)d_in[5];
    float* out = (float*)d_out;

    dim3 gproj(H_ / 64, (B_ * Q_) / 64, 2);
    proj_gemm<<<gproj, 256>>>(queries, W_q, keys, W_k);

    dim3 gscores(K_ / 64, Q_ / 64, B_);
    scores_f16<<<gscores, 256>>>(w_v);

    dim3 gav(16, B_);
    softmax_av<<<gav, 256>>>(values, out);
}

// round 3
// speedup vs baseline: 1.0241x; 1.0241x over previous
#include <cuda_runtime.h>
#include <cuda_fp16.h>
#include <cstdint>

#define B_  16
#define Q_  256
#define K_  256
#define H_  256
#define DV_ 256

__device__ float g_qp[B_ * Q_ * H_];
__device__ float g_kp[B_ * K_ * H_];
__device__ float g_scores[B_ * Q_ * K_];

__device__ __forceinline__ unsigned long long pack2(float lo, float hi) {
    unsigned long long r;
    asm("mov.b64 %0, {%1, %2};" : "=l"(r) : "f"(lo), "f"(hi));
    return r;
}
__device__ __forceinline__ float2 unpack2(unsigned long long v) {
    float2 f;
    asm("mov.b64 {%0, %1}, %2;" : "=f"(f.x), "=f"(f.y) : "l"(v));
    return f;
}
__device__ __forceinline__ void ffma2(unsigned long long& acc,
                                      unsigned long long a, unsigned long long b) {
    asm("fma.rn.f32x2 %0, %1, %2, %0;" : "+l"(acc) : "l"(a), "l"(b));
}
__device__ __forceinline__ __half2 tanh2_h(__half2 x) {
    __half2 y;
    asm("tanh.approx.f16x2 %0, %1;"
        : "=r"(*reinterpret_cast<unsigned*>(&y))
        : "r"(*reinterpret_cast<const unsigned*>(&x)));
    return y;
}
__device__ __forceinline__ void cp16(uint32_t dst, const void* src) {
    asm volatile("cp.async.cg.shared.global [%0], [%1], 16;" :: "r"(dst), "l"(src));
}

// ---------------------------------------------------------------------------
// Kernel 1: projection GEMM  C[M,256] = A[M,256] * W[256,256]^T  (scalar FFMA)
// blockIdx.z: 0 -> queries/W_q -> g_qp ; 1 -> keys/W_k -> g_kp
// ---------------------------------------------------------------------------
__global__ __launch_bounds__(256) void proj_gemm(const float* __restrict__ Aq,
                                                 const float* __restrict__ Wq,
                                                 const float* __restrict__ Ak,
                                                 const float* __restrict__ Wk) {
    constexpr int BM = 64, BN = 64, BK = 32;
    __shared__ float As[BK][BM + 4];
    __shared__ float Bs[BK][BN + 4];

    const float* A;
    const float* W;
    float* C;
    if (blockIdx.z == 0) { A = Aq; W = Wq; C = g_qp; }
    else                 { A = Ak; W = Wk; C = g_kp; }

    const int tid = threadIdx.x;
    const int m0 = blockIdx.y * BM;
    const int n0 = blockIdx.x * BN;
    const int ty = tid >> 4;
    const int tx = tid & 15;

    float acc[4][4];
#pragma unroll
    for (int i = 0; i < 4; i++)
#pragma unroll
        for (int j = 0; j < 4; j++) acc[i][j] = 0.0f;

    const int lr = tid >> 3;
    const int lc = (tid & 7) * 4;

    for (int kt = 0; kt < H_; kt += BK) {
        float4 a0 = *(const float4*)&A[(m0 + lr) * H_ + kt + lc];
        float4 a1 = *(const float4*)&A[(m0 + lr + 32) * H_ + kt + lc];
        float4 b0 = *(const float4*)&W[(n0 + lr) * H_ + kt + lc];
        float4 b1 = *(const float4*)&W[(n0 + lr + 32) * H_ + kt + lc];

        As[lc + 0][lr] = a0.x; As[lc + 1][lr] = a0.y;
        As[lc + 2][lr] = a0.z; As[lc + 3][lr] = a0.w;
        As[lc + 0][lr + 32] = a1.x; As[lc + 1][lr + 32] = a1.y;
        As[lc + 2][lr + 32] = a1.z; As[lc + 3][lr + 32] = a1.w;
        Bs[lc + 0][lr] = b0.x; Bs[lc + 1][lr] = b0.y;
        Bs[lc + 2][lr] = b0.z; Bs[lc + 3][lr] = b0.w;
        Bs[lc + 0][lr + 32] = b1.x; Bs[lc + 1][lr + 32] = b1.y;
        Bs[lc + 2][lr + 32] = b1.z; Bs[lc + 3][lr + 32] = b1.w;

        __syncthreads();

#pragma unroll
        for (int kk = 0; kk < BK; kk++) {
            float a[4], b[4];
#pragma unroll
            for (int i = 0; i < 4; i++) a[i] = As[kk][ty * 4 + i];
#pragma unroll
            for (int j = 0; j < 4; j++) b[j] = Bs[kk][tx * 4 + j];
#pragma unroll
            for (int i = 0; i < 4; i++)
#pragma unroll
                for (int j = 0; j < 4; j++) acc[i][j] += a[i] * b[j];
        }
        __syncthreads();
    }

#pragma unroll
    for (int i = 0; i < 4; i++) {
        float4 v;
        v.x = acc[i][0]; v.y = acc[i][1]; v.z = acc[i][2]; v.w = acc[i][3];
        *(float4*)&C[(m0 + ty * 4 + i) * H_ + n0 + tx * 4] = v;
    }
}

// ---------------------------------------------------------------------------
// Kernel 2: scores[b,q,k] = sum_h w_v[h] * tanh(qp+kp)
// Tiles converted to __half2 ONCE at load; inner loop = HADD2 + tanh.f16x2 +
// HFMA2 only. 64x64 tile, 4x4 per thread, 2 tanh per MUFU op.
// ---------------------------------------------------------------------------
__global__ __launch_bounds__(256) void scores_f16(const float* __restrict__ wv) {
    const int b = blockIdx.z;
    const int q0 = blockIdx.y * 64;
    const int k0 = blockIdx.x * 64;

    __shared__ __half2 qs[64][17];   // 16 half2 per row + 1 pad (68B stride)
    __shared__ __half2 ks[64][17];
    __shared__ __half2 sw2[128];

    const int tid = threadIdx.x;
    if (tid < 128) sw2[tid] = __floats2half2_rn(wv[2 * tid], wv[2 * tid + 1]);

    const int ty = tid >> 4;       // q rows ty*4..+3
    const int tx = tid & 15;       // k rows tx*4..+3
    const int lr = tid >> 3;       // 0..31
    const int lc = (tid & 7) * 4;  // 0..28 (float index in 32-chunk)

    const float* qb = g_qp + (b * Q_ + q0) * H_;
    const float* kb = g_kp + (b * K_ + k0) * H_;

    float facc[4][4];
#pragma unroll
    for (int i = 0; i < 4; i++)
#pragma unroll
        for (int j = 0; j < 4; j++) facc[i][j] = 0.f;

    for (int hc = 0; hc < H_; hc += 32) {
        __syncthreads();
        {
            float4 a0 = *(const float4*)&qb[lr * H_ + hc + lc];
            float4 a1 = *(const float4*)&qb[(lr + 32) * H_ + hc + lc];
            float4 c0 = *(const float4*)&kb[lr * H_ + hc + lc];
            float4 c1 = *(const float4*)&kb[(lr + 32) * H_ + hc + lc];
            qs[lr][lc / 2]          = __floats2half2_rn(a0.x, a0.y);
            qs[lr][lc / 2 + 1]      = __floats2half2_rn(a0.z, a0.w);
            qs[lr + 32][lc / 2]     = __floats2half2_rn(a1.x, a1.y);
            qs[lr + 32][lc / 2 + 1] = __floats2half2_rn(a1.z, a1.w);
            ks[lr][lc / 2]          = __floats2half2_rn(c0.x, c0.y);
            ks[lr][lc / 2 + 1]      = __floats2half2_rn(c0.z, c0.w);
            ks[lr + 32][lc / 2]     = __floats2half2_rn(c1.x, c1.y);
            ks[lr + 32][lc / 2 + 1] = __floats2half2_rn(c1.z, c1.w);
        }
        __syncthreads();

#pragma unroll
        for (int g = 0; g < 4; g++) {
            __half2 cacc[4][4];
            const __half2 z2 = __float2half2_rn(0.f);
#pragma unroll
            for (int i = 0; i < 4; i++)
#pragma unroll
                for (int j = 0; j < 4; j++) cacc[i][j] = z2;

#pragma unroll
            for (int s = 0; s < 4; s++) {
                const int h2 = g * 4 + s;
                __half2 q2[4], k2[4];
#pragma unroll
                for (int i = 0; i < 4; i++) q2[i] = qs[ty * 4 + i][h2];
#pragma unroll
                for (int j = 0; j < 4; j++) k2[j] = ks[tx * 4 + j][h2];
                const __half2 w2 = sw2[(hc >> 1) + h2];
#pragma unroll
                for (int i = 0; i < 4; i++)
#pragma unroll
                    for (int j = 0; j < 4; j++) {
                        __half2 t = tanh2_h(__hadd2(q2[i], k2[j]));
                        cacc[i][j] = __hfma2(t, w2, cacc[i][j]);
                    }
            }
#pragma unroll
            for (int i = 0; i < 4; i++)
#pragma unroll
                for (int j = 0; j < 4; j++) {
                    float2 f = __half22float2(cacc[i][j]);
                    facc[i][j] += f.x + f.y;
                }
        }
    }

    float* sbase = g_scores + (b * Q_ + q0 + ty * 4) * K_ + k0 + tx * 4;
#pragma unroll
    for (int i = 0; i < 4; i++)
        *(float4*)&sbase[i * K_] = make_float4(facc[i][0], facc[i][1], facc[i][2], facc[i][3]);
}

// ---------------------------------------------------------------------------
// Kernel 3: fused row-softmax + out = attn @ V  (unchanged from R2)
// ---------------------------------------------------------------------------
__global__ __launch_bounds__(256) void softmax_av(const float* __restrict__ V,
                                                  float* __restrict__ out) {
    const int b = blockIdx.y;
    const int q0 = (blockIdx.x >> 1) * 32;
    const int c0 = (blockIdx.x & 1) * 128;

    __shared__ __align__(16) float sattn[32][256];
    __shared__ __align__(16) float vs[2][32][132];

    const int tid = threadIdx.x;
    const int w = tid >> 5;
    const int lane = tid & 31;

#pragma unroll
    for (int i = 0; i < 4; i++) {
        const int r = w + 8 * i;
        const float* srow = g_scores + (b * Q_ + q0 + r) * K_;
        float v[8];
        float mx = -1e30f;
#pragma unroll
        for (int j = 0; j < 8; j++) {
            v[j] = srow[lane + 32 * j];
            mx = fmaxf(mx, v[j]);
        }
#pragma unroll
        for (int off = 16; off; off >>= 1)
            mx = fmaxf(mx, __shfl_xor_sync(0xffffffffu, mx, off));
        float s = 0.f;
#pragma unroll
        for (int j = 0; j < 8; j++) {
            v[j] = __expf(v[j] - mx);
            s += v[j];
        }
#pragma unroll
        for (int off = 16; off; off >>= 1)
            s += __shfl_xor_sync(0xffffffffu, s, off);
        const float inv = 1.0f / s;
#pragma unroll
        for (int j = 0; j < 8; j++) sattn[r][lane + 32 * j] = v[j] * inv;
    }

    const int r0 = 4 * w;
    unsigned long long acc2[4][2];
#pragma unroll
    for (int r = 0; r < 4; r++) { acc2[r][0] = pack2(0.f, 0.f); acc2[r][1] = pack2(0.f, 0.f); }

    const int vr = tid >> 3;
    const int vc = (tid & 7) * 16;

    auto stage = [&](int kc, int buf) {
        const float* src = V + (size_t)(b * K_ + kc * 32 + vr) * DV_ + c0 + vc;
        uint32_t dst = (uint32_t)__cvta_generic_to_shared(&vs[buf][vr][vc]);
#pragma unroll
        for (int j = 0; j < 4; j++) cp16(dst + j * 16, src + j * 4);
        asm volatile("cp.async.commit_group;");
    };

    stage(0, 0);

    for (int kc = 0; kc < 8; kc++) {
        if (kc < 7) {
            stage(kc + 1, (kc + 1) & 1);
            asm volatile("cp.async.wait_group 1;");
        } else {
            asm volatile("cp.async.wait_group 0;");
        }
        __syncthreads();

        const int buf = kc & 1;
#pragma unroll
        for (int k4 = 0; k4 < 8; k4++) {
            float4 a4[4];
#pragma unroll
            for (int r = 0; r < 4; r++)
                a4[r] = *(const float4*)&sattn[r0 + r][kc * 32 + k4 * 4];
#pragma unroll
            for (int kk = 0; kk < 4; kk++) {
                float4 v = *(const float4*)&vs[buf][k4 * 4 + kk][lane * 4];
                unsigned long long v01 = pack2(v.x, v.y);
                unsigned long long v23 = pack2(v.z, v.w);
#pragma unroll
                for (int r = 0; r < 4; r++) {
                    float av = ((const float*)&a4[r])[kk];
                    unsigned long long ad = pack2(av, av);
                    ffma2(acc2[r][0], ad, v01);
                    ffma2(acc2[r][1], ad, v23);
                }
            }
        }
        __syncthreads();
    }

#pragma unroll
    for (int r = 0; r < 4; r++) {
        float2 p0 = unpack2(acc2[r][0]);
        float2 p1 = unpack2(acc2[r][1]);
        *(float4*)&out[(size_t)(b * Q_ + q0 + r0 + r) * DV_ + c0 + lane * 4] =
            make_float4(p0.x, p0.y, p1.x, p1.y);
    }
}

// ---------------------------------------------------------------------------
extern "C" void kernel_launch(void* const* d_in, const int* in_sizes, int n_in,
                              void* d_out, int out_size) {
    const float* queries = (const float*)d_in[0];
    const float* keys    = (const float*)d_in[1];
    const float* values  = (const float*)d_in[2];
    const float* W_q     = (const float*)d_in[3];
    const float* W_k     = (const float*)d_in[4];
    const float* w_v     = (const float*)d_in[5];
    float* out = (float*)d_out;

    dim3 gproj(H_ / 64, (B_ * Q_) / 64, 2);
    proj_gemm<<<gproj, 256>>>(queries, W_q, keys, W_k);

    dim3 gscores(K_ / 64, Q_ / 64, B_);
    scores_f16<<<gscores, 256>>>(w_v);

    dim3 gav(16, B_);
    softmax_av<<<gav, 256>>>(values, out);
}